// round 4
// baseline (speedup 1.0000x reference)
#include <cuda_runtime.h>
#include <math.h>

#define NN   50000
#define EE   800000
#define CC   64
#define HH   8
#define NRBF 50
#define NSLOT (NN * CC)
#define INV_DEG   0.25f
#define RSQRT3    0.57735026918962576f
#define RSQRT2    0.70710678118654752f
#define RBF_START 0.006737946999085467f
#define PI_OVER_CUT 0.6283185307179586f

// ---------------- device scratch (static, allocation-free) ----------------
__device__ __align__(16) float    g_f0  [NSLOT];
__device__ __align__(16) float    g_f1  [NSLOT * 3];            // [n][c][i]
__device__ __align__(16) float    g_acc0[NSLOT];
__device__ __align__(16) float    g_acc1[3 * NSLOT];            // [i][n][c]
__device__ __align__(16) float    g_agg0[NSLOT];
__device__ __align__(16) float    g_agg1[3 * NSLOT];
__device__ __align__(16) float    g_z   [NN * HH];
__device__ __align__(16) unsigned g_amax[NN * HH];
__device__ __align__(16) float    g_Y1  [3 * EE];               // [i][e]
__device__ __align__(16) float    g_a   [HH * EE];              // [h][e]
__device__ __align__(16) float    g_wattn[320 * (size_t)EE];    // [j][e]
__device__ __align__(16) float    g_msg0 [CC * (size_t)EE];     // [c][e]
__device__ __align__(16) float    g_msg1 [3 * CC * (size_t)EE]; // [(c*3+i)][e]

// ---------------- helpers ----------------
__device__ __forceinline__ unsigned fenc(float x) {
    unsigned b = __float_as_uint(x);
    return (b & 0x80000000u) ? ~b : (b | 0x80000000u);
}
__device__ __forceinline__ float fdec(unsigned u) {
    return __uint_as_float((u & 0x80000000u) ? (u & 0x7FFFFFFFu) : ~u);
}
__device__ __forceinline__ float sigf(float x)  { return 1.0f / (1.0f + expf(-x)); }
__device__ __forceinline__ float siluf(float x) { return x * sigf(x); }

__device__ __forceinline__ void zero16(float* v) {
#pragma unroll
    for (int t = 0; t < 16; t++) v[t] = 0.f;
}
__device__ __forceinline__ void load16(float* v, const float* p) {
#pragma unroll
    for (int t = 0; t < 4; t++) {
        float4 b = __ldg(reinterpret_cast<const float4*>(p) + t);
        v[t*4+0]=b.x; v[t*4+1]=b.y; v[t*4+2]=b.z; v[t*4+3]=b.w;
    }
}
// acc[0..15] += sum_k x[k] * W[k][4*col4 .. 4*col4+15]; W row-major, ld4 = row width/4
__device__ __forceinline__ void gemm16(float* acc, const float* x, int K,
                                       const float* W, int ld4, int col4) {
    const float4* W4 = reinterpret_cast<const float4*>(W) + col4;
#pragma unroll 2
    for (int k = 0; k < K; k++) {
        float xv = x[k];
        const float4* wr = W4 + k * ld4;
        float4 w;
        w=__ldg(wr+0); acc[0]+=xv*w.x; acc[1]+=xv*w.y; acc[2]+=xv*w.z; acc[3]+=xv*w.w;
        w=__ldg(wr+1); acc[4]+=xv*w.x; acc[5]+=xv*w.y; acc[6]+=xv*w.z; acc[7]+=xv*w.w;
        w=__ldg(wr+2); acc[8]+=xv*w.x; acc[9]+=xv*w.y; acc[10]+=xv*w.z; acc[11]+=xv*w.w;
        w=__ldg(wr+3); acc[12]+=xv*w.x; acc[13]+=xv*w.y; acc[14]+=xv*w.z; acc[15]+=xv*w.w;
    }
}

// ---------------- K0: zero accumulators ----------------
__global__ void k_zero() {
    int i = blockIdx.x * blockDim.x + threadIdx.x;
    if (i < 3 * NSLOT) { g_acc1[i] = 0.f; g_agg1[i] = 0.f; }
    if (i < NSLOT)     { g_acc0[i] = 0.f; g_agg0[i] = 0.f; }
    if (i < NN * HH)   { g_z[i] = 0.f; g_amax[i] = 0u; }
}

// ---------------- K1: edge geometry + RBF MLP + deg scatter + w_attn ----------------
__global__ void __launch_bounds__(256) k_edge1(
    const float* __restrict__ pos,
    const int* __restrict__ esrc, const int* __restrict__ edst,
    const float* __restrict__ W1, const float* __restrict__ B1,
    const float* __restrict__ W2, const float* __restrict__ B2,
    const float* __restrict__ WD, const float* __restrict__ BD,
    const float* __restrict__ WA, const float* __restrict__ BA,
    const float* __restrict__ expw)
{
    __shared__ float sRBF[64 * 53];
    __shared__ float sH1[64 * 65];
    __shared__ float sH2[64 * 65];
    __shared__ float sY[64 * 3];
    __shared__ float sExp[64];
    __shared__ float sCut[64];
    __shared__ int   sDst[64];

    int tid = threadIdx.x;
    int eb = blockIdx.x * 64;

    if (tid < 64) {
        int e = eb + tid;
        int s = __ldg(esrc + e), d = __ldg(edst + e);
        float vx = __ldg(pos + d*3+0) - __ldg(pos + s*3+0);
        float vy = __ldg(pos + d*3+1) - __ldg(pos + s*3+1);
        float vz = __ldg(pos + d*3+2) - __ldg(pos + s*3+2);
        float dist = sqrtf(vx*vx + vy*vy + vz*vz + 1e-9f);
        float rd = 1.0f / dist;
        float y0 = vx*rd, y1 = vy*rd, y2 = vz*rd;
        g_Y1[e] = y0; g_Y1[EE+e] = y1; g_Y1[2*EE+e] = y2;
        sY[tid*3+0]=y0; sY[tid*3+1]=y1; sY[tid*3+2]=y2;
        sDst[tid] = d;
        sExp[tid] = expf(-dist);
        sCut[tid] = (dist < 5.0f) ? 0.5f * (cosf(PI_OVER_CUT * dist) + 1.0f) : 0.0f;
    }
    __syncthreads();

    {   // RBF features, row stride 53 (conflict-free)
        const float OM = 1.0f - RBF_START;
        const float BD_ = 0.04f * OM;
        const float BETA = 1.0f / (BD_ * BD_);
        const float STEP = OM / 49.0f;
        for (int i = tid; i < 64 * NRBF; i += 256) {
            int el = i / NRBF, k = i - el * NRBF;
            float t = sExp[el] - (RBF_START + STEP * (float)k);
            sRBF[el * 53 + k] = sCut[el] * expf(-BETA * t * t);
        }
    }
    __syncthreads();

    int el = tid & 63, jg = tid >> 6;
    float v[16];

    load16(v, B1 + jg * 16);
    gemm16(v, sRBF + el * 53, NRBF, W1, 16, jg * 4);
#pragma unroll
    for (int q = 0; q < 16; q++) sH1[el*65 + jg*16 + q] = siluf(v[q]);
    __syncthreads();

    load16(v, B2 + jg * 16);
    gemm16(v, sH1 + el * 65, CC, W2, 16, jg * 4);
#pragma unroll
    for (int q = 0; q < 16; q++) sH2[el*65 + jg*16 + q] = siluf(v[q]);
    __syncthreads();

    const float* x2 = sH2 + el * 65;
    int e = eb + el;
    int dst = sDst[el];
    float y0 = sY[el*3+0], y1 = sY[el*3+1], y2 = sY[el*3+2];
    int ab = dst * CC + jg * 16;

    // w_deg[:, :64] -> e0 scatter
    load16(v, BD + jg * 16);
    gemm16(v, x2, CC, WD, 32, jg * 4);
#pragma unroll
    for (int q = 0; q < 16; q++)
        atomicAdd(&g_acc0[ab + q], v[q] * __ldg(expw + jg*16 + q));

    // w_deg[:, 64:] -> e1 scatter (x Y1)
    load16(v, BD + 64 + jg * 16);
    gemm16(v, x2, CC, WD, 32, 16 + jg * 4);
#pragma unroll
    for (int q = 0; q < 16; q++) {
        float ev = v[q] * __ldg(expw + jg*16 + q);
        atomicAdd(&g_acc1[0*NSLOT + ab + q], ev * y0);
        atomicAdd(&g_acc1[1*NSLOT + ab + q], ev * y1);
        atomicAdd(&g_acc1[2*NSLOT + ab + q], ev * y2);
    }

    // w_attn (320 cols) -> [j][e]
#pragma unroll
    for (int cb = 0; cb < 5; cb++) {
        load16(v, BA + cb * 64 + jg * 16);
        gemm16(v, x2, CC, WA, 80, cb * 16 + jg * 4);
        size_t base = (size_t)(cb * 64 + jg * 16) * EE + e;
#pragma unroll
        for (int q = 0; q < 16; q++) g_wattn[base + (size_t)q * EE] = v[q];
    }
}

// ---------------- K2: node deg projection (32 nodes/block, 128 thr) ----------------
__global__ void __launch_bounds__(128) k_node_deg(
    const float* __restrict__ embed_W, const int* __restrict__ atom,
    const float* __restrict__ P0, const float* __restrict__ P1)
{
    __shared__ float b0[32*65], b1[32*65], b2[32*65], b3[32*65];
    int tid = threadIdx.x;
    int nb = blockIdx.x * 32;

    for (int i = tid; i < 2048; i += 128) {
        int r = i >> 6, c = i & 63, n = nb + r;
        bool ok = (n < NN);
        b0[r*65+c] = ok ? g_acc0[n*CC + c] : 0.f;
        b1[r*65+c] = ok ? g_acc1[0*NSLOT + n*CC + c] : 0.f;
        b2[r*65+c] = ok ? g_acc1[1*NSLOT + n*CC + c] : 0.f;
        b3[r*65+c] = ok ? g_acc1[2*NSLOT + n*CC + c] : 0.f;
    }
    __syncthreads();

    int nl = tid & 31, jg = tid >> 5;
    int n = nb + nl;
    if (n >= NN) return;
    int at = __ldg(atom + n);

    float v[16];
    zero16(v);
    gemm16(v, b0 + nl*65, CC, P0, 16, jg * 4);
#pragma unroll
    for (int q = 0; q < 16; q++)
        g_f0[n*CC + jg*16 + q] = __ldg(embed_W + at*CC + jg*16 + q) + INV_DEG * v[q];

    const float* planes[3] = { b1, b2, b3 };
#pragma unroll
    for (int i = 0; i < 3; i++) {
        float t[16]; zero16(t);
        gemm16(t, planes[i] + nl*65, CC, P1, 16, jg * 4);
#pragma unroll
        for (int q = 0; q < 16; q++)
            g_f1[n*192 + (jg*16+q)*3 + i] = INV_DEG * t[q];
    }
}

// ---------------- K3: edge messages + logits + segment max ----------------
__global__ void __launch_bounds__(256) k_edge2(
    const int* __restrict__ esrc, const int* __restrict__ edst,
    const float* __restrict__ alpha)
{
    int tid = threadIdx.x;
    int el = tid & 63, jg = tid >> 6;
    int e = blockIdx.x * 64 + el;

    int src = __ldg(esrc + e);
    int dst = __ldg(edst + e);
    float y0 = g_Y1[e], y1 = g_Y1[EE+e], y2 = g_Y1[2*EE+e];

    float s0[16];
    load16(s0, g_f0 + src*CC + jg*16);

    float aA = 0.f, aB = 0.f;
#pragma unroll
    for (int q = 0; q < 16; q++) {
        int c = jg * 16 + q;
        const float* s1p = g_f1 + src*192 + c*3;
        float s1x = __ldg(s1p+0), s1y = __ldg(s1p+1), s1z = __ldg(s1p+2);
        float w0 = g_wattn[(size_t)(c      ) * EE + e];
        float w1 = g_wattn[(size_t)(c +  64) * EE + e];
        float w2 = g_wattn[(size_t)(c + 128) * EE + e];
        float w3 = g_wattn[(size_t)(c + 192) * EE + e];
        float w4 = g_wattn[(size_t)(c + 256) * EE + e];

        float sd = s1x*y0 + s1y*y1 + s1z*y2;
        float m0 = w0 * s0[q] + w3 * sd * RSQRT3;
        float cr0 = s1y*y2 - s1z*y1, cr1 = s1z*y0 - s1x*y2, cr2 = s1x*y1 - s1y*y0;
        float ws = w1 * s0[q];
        float m1x = ws*y0 + w2*s1x + w4*cr0*RSQRT2;
        float m1y = ws*y1 + w2*s1y + w4*cr1*RSQRT2;
        float m1z = ws*y2 + w2*s1z + w4*cr2*RSQRT2;

        g_msg0[(size_t)c * EE + e] = m0;
        g_msg1[(size_t)(c*3+0) * EE + e] = m1x;
        g_msg1[(size_t)(c*3+1) * EE + e] = m1y;
        g_msg1[(size_t)(c*3+2) * EE + e] = m1z;

        float slr = 0.2f * m0 + 0.8f * m0 * sigf(m0);
        float ad = __ldg(alpha + c);
        if (q < 8) aA += slr * ad; else aB += slr * ad;
    }
    int h0 = jg * 2;
    g_a[(size_t)h0     * EE + e] = aA;
    g_a[(size_t)(h0+1) * EE + e] = aB;
    atomicMax(&g_amax[dst*HH + h0],   fenc(aA));
    atomicMax(&g_amax[dst*HH + h0+1], fenc(aB));
}

// ---------------- K4: ea + scatter z, ea*msg ----------------
__global__ void __launch_bounds__(256) k_edge3(const int* __restrict__ edst)
{
    int tid = threadIdx.x;
    int el = tid & 63, jg = tid >> 6;
    int e = blockIdx.x * 64 + el;
    int dst = __ldg(edst + e);
    int h0 = jg * 2;

    float eaA = expf(g_a[(size_t)h0    *EE + e] - fdec(g_amax[dst*HH + h0]));
    float eaB = expf(g_a[(size_t)(h0+1)*EE + e] - fdec(g_amax[dst*HH + h0+1]));
    atomicAdd(&g_z[dst*HH + h0],   eaA);
    atomicAdd(&g_z[dst*HH + h0+1], eaB);

    int ab = dst * CC + jg * 16;
#pragma unroll
    for (int q = 0; q < 16; q++) {
        int c = jg * 16 + q;
        float ea = (q < 8) ? eaA : eaB;
        atomicAdd(&g_agg0[ab + q], ea * g_msg0[(size_t)c * EE + e]);
        atomicAdd(&g_agg1[0*NSLOT + ab + q], ea * g_msg1[(size_t)(c*3+0)*EE + e]);
        atomicAdd(&g_agg1[1*NSLOT + ab + q], ea * g_msg1[(size_t)(c*3+1)*EE + e]);
        atomicAdd(&g_agg1[2*NSLOT + ab + q], ea * g_msg1[(size_t)(c*3+2)*EE + e]);
    }
}

// ---------------- K5a: out projection (updates g_f0/g_f1 in place) ----------------
__global__ void __launch_bounds__(128) k_node_out(
    const float* __restrict__ OP0, const float* __restrict__ OP1)
{
    __shared__ float b0[32*65], b1[32*65], b2[32*65], b3[32*65];
    __shared__ float zt[32*8];
    int tid = threadIdx.x;
    int nb = blockIdx.x * 32;

    for (int i = tid; i < 256; i += 128) {
        int r = i >> 3, h = i & 7, n = nb + r;
        float z = (n < NN) ? g_z[n*HH + h] : 0.f;
        zt[i] = (z > 0.f) ? 1.0f / z : 0.f;
    }
    __syncthreads();
    for (int i = tid; i < 2048; i += 128) {
        int r = i >> 6, c = i & 63, n = nb + r;
        bool ok = (n < NN);
        float s = zt[r*8 + (c >> 3)];
        b0[r*65+c] = ok ? g_agg0[n*CC + c] * s : 0.f;
        b1[r*65+c] = ok ? g_agg1[0*NSLOT + n*CC + c] * s : 0.f;
        b2[r*65+c] = ok ? g_agg1[1*NSLOT + n*CC + c] * s : 0.f;
        b3[r*65+c] = ok ? g_agg1[2*NSLOT + n*CC + c] * s : 0.f;
    }
    __syncthreads();

    int nl = tid & 31, jg = tid >> 5;
    int n = nb + nl;
    if (n >= NN) return;

    float v[16];
    zero16(v);
    gemm16(v, b0 + nl*65, CC, OP0, 16, jg * 4);
#pragma unroll
    for (int q = 0; q < 16; q++) g_f0[n*CC + jg*16 + q] += v[q];

    const float* planes[3] = { b1, b2, b3 };
#pragma unroll
    for (int i = 0; i < 3; i++) {
        float t[16]; zero16(t);
        gemm16(t, planes[i] + nl*65, CC, OP1, 16, jg * 4);
#pragma unroll
        for (int q = 0; q < 16; q++)
            g_f1[n*192 + (jg*16+q)*3 + i] += t[q];
    }
}

// ---------------- K5b: FFN + final output ----------------
__global__ void __launch_bounds__(128) k_node_ffn(
    const float* __restrict__ W1s, const float* __restrict__ B1s,
    const float* __restrict__ W1v,
    const float* __restrict__ W2s, const float* __restrict__ B2s,
    const float* __restrict__ W2v,
    float* __restrict__ out)
{
    __shared__ float b0[32*65], b1[32*65], b2[32*65], b3[32*65];
    int tid = threadIdx.x;
    int nb = blockIdx.x * 32;

    for (int i = tid; i < 2048; i += 128) {
        int r = i >> 6, c = i & 63, n = nb + r;
        bool ok = (n < NN);
        b0[r*65+c] = ok ? g_f0[n*CC + c] : 0.f;
        b1[r*65+c] = ok ? g_f1[n*192 + c*3 + 0] : 0.f;
        b2[r*65+c] = ok ? g_f1[n*192 + c*3 + 1] : 0.f;
        b3[r*65+c] = ok ? g_f1[n*192 + c*3 + 2] : 0.f;
    }
    __syncthreads();

    int nl = tid & 31, jg = tid >> 5;
    int n = nb + nl;
    bool valid = (n < NN);

    float ms[16], gt[16], mv[48];
    {
        float hA[16], hB[16];
        load16(hA, B1s + jg * 16);
        load16(hB, B1s + 64 + jg * 16);
        gemm16(hA, b0 + nl*65, CC, W1s, 32, jg * 4);
        gemm16(hB, b0 + nl*65, CC, W1s, 32, 16 + jg * 4);
#pragma unroll
        for (int q = 0; q < 16; q++) { ms[q] = siluf(hA[q]); gt[q] = sigf(hB[q]); }
        const float* planes[3] = { b1, b2, b3 };
#pragma unroll
        for (int i = 0; i < 3; i++) {
            float t[16]; zero16(t);
            gemm16(t, planes[i] + nl*65, CC, W1v, 16, jg * 4);
#pragma unroll
            for (int q = 0; q < 16; q++) mv[i*16 + q] = t[q] * gt[q];
        }
    }
    __syncthreads();
    // overwrite tiles with mid_s / mid_v
#pragma unroll
    for (int q = 0; q < 16; q++) {
        int c = jg * 16 + q;
        b0[nl*65 + c] = ms[q];
        b1[nl*65 + c] = mv[q];
        b2[nl*65 + c] = mv[16 + q];
        b3[nl*65 + c] = mv[32 + q];
    }
    __syncthreads();

    if (!valid) return;

    float v[16];
    load16(v, B2s + jg * 16);
    gemm16(v, b0 + nl*65, CC, W2s, 16, jg * 4);
#pragma unroll
    for (int q = 0; q < 16; q++) {
        int c = jg * 16 + q;
        out[(size_t)n*256 + c] = g_f0[n*CC + c] + v[q];
    }
    const float* planes[3] = { b1, b2, b3 };
#pragma unroll
    for (int i = 0; i < 3; i++) {
        float t[16]; zero16(t);
        gemm16(t, planes[i] + nl*65, CC, W2v, 16, jg * 4);
#pragma unroll
        for (int q = 0; q < 16; q++) {
            int c = jg * 16 + q;
            out[(size_t)n*256 + 64 + c*3 + i] = g_f1[n*192 + c*3 + i] + t[q];
        }
    }
}

// ---------------- launch ----------------
extern "C" void kernel_launch(void* const* d_in, const int* in_sizes, int n_in,
                              void* d_out, int out_size)
{
    const float* pos   = (const float*)d_in[0];
    const float* embed = (const float*)d_in[1];
    const float* expw  = (const float*)d_in[2];
    const float* W1    = (const float*)d_in[3];
    const float* B1    = (const float*)d_in[4];
    const float* W2    = (const float*)d_in[5];
    const float* B2    = (const float*)d_in[6];
    const float* WD    = (const float*)d_in[7];
    const float* BDg   = (const float*)d_in[8];
    const float* WA    = (const float*)d_in[9];
    const float* BA    = (const float*)d_in[10];
    const float* P0    = (const float*)d_in[11];
    const float* P1    = (const float*)d_in[12];
    const float* alpha = (const float*)d_in[13];
    const float* OP0   = (const float*)d_in[14];
    const float* OP1   = (const float*)d_in[15];
    const float* W1s   = (const float*)d_in[16];
    const float* B1s   = (const float*)d_in[17];
    const float* W1v   = (const float*)d_in[18];
    const float* W2s   = (const float*)d_in[19];
    const float* B2s   = (const float*)d_in[20];
    const float* W2v   = (const float*)d_in[21];
    const int*   atom  = (const int*)d_in[22];
    const int*   esrc  = (const int*)d_in[23];
    const int*   edst  = (const int*)d_in[24];
    float* out = (float*)d_out;

    int eblk = EE / 64;                 // 12500
    int nblk = (NN + 31) / 32;          // 1563

    k_zero<<<(3 * NSLOT + 255) / 256, 256>>>();
    k_edge1<<<eblk, 256>>>(pos, esrc, edst, W1, B1, W2, B2, WD, BDg, WA, BA, expw);
    k_node_deg<<<nblk, 128>>>(embed, atom, P0, P1);
    k_edge2<<<eblk, 256>>>(esrc, edst, alpha);
    k_edge3<<<eblk, 256>>>(edst);
    k_node_out<<<nblk, 128>>>(OP0, OP1);
    k_node_ffn<<<nblk, 128>>>(W1s, B1s, W1v, W2s, B2s, W2v, out);
}

// round 16
// speedup vs baseline: 1.3063x; 1.3063x over previous
#include <cuda_runtime.h>
#include <math.h>

#define NN   50000
#define EE   800000
#define CC   64
#define HH   8
#define NRBF 50
#define NSLOT (NN * CC)
#define INV_DEG   0.25f
#define RSQRT3    0.57735026918962576f
#define RSQRT2    0.70710678118654752f
#define RBF_START 0.006737946999085467f
#define PI_OVER_CUT 0.6283185307179586f

// ---------------- device scratch (static, allocation-free) ----------------
__device__ __align__(16) float g_f0 [NSLOT];
__device__ __align__(16) float g_f1 [NSLOT * 3];                 // [n][c][i]
__device__ __align__(16) float g_Y1 [3 * EE];                    // [i][e]
__device__ __align__(16) float g_a  [(size_t)EE * HH];           // [e][h]
__device__ __align__(16) float g_deg[(size_t)EE * 128];          // [e][{e0w[64],e1w[64]}]
__device__ __align__(16) float g_wat[(size_t)EE * 320];          // [e][k*64+c]
__device__ __align__(16) float g_msg[(size_t)EE * 256];          // [e][{m0[64],m1[192]}]
__device__ int g_cnt[NN];
__device__ int g_rowptr[NN + 1];
__device__ int g_fill[NN];
__device__ int g_eid[EE];

// ---------------- helpers ----------------
__device__ __forceinline__ float sigf(float x)  { return 1.0f / (1.0f + expf(-x)); }
__device__ __forceinline__ float siluf(float x) { return x * sigf(x); }

__device__ __forceinline__ void zero16(float* v) {
#pragma unroll
    for (int t = 0; t < 16; t++) v[t] = 0.f;
}
__device__ __forceinline__ void load16(float* v, const float* p) {
#pragma unroll
    for (int t = 0; t < 4; t++) {
        float4 b = __ldg(reinterpret_cast<const float4*>(p) + t);
        v[t*4+0]=b.x; v[t*4+1]=b.y; v[t*4+2]=b.z; v[t*4+3]=b.w;
    }
}
__device__ __forceinline__ void store16(float* p, const float* v) {
    float4* p4 = reinterpret_cast<float4*>(p);
#pragma unroll
    for (int t = 0; t < 4; t++)
        p4[t] = make_float4(v[t*4+0], v[t*4+1], v[t*4+2], v[t*4+3]);
}
// acc[0..15] += sum_k x[k] * W[k][4*col4 .. 4*col4+15]; W row-major, ld4 = row/4
__device__ __forceinline__ void gemm16(float* acc, const float* x, int K,
                                       const float* W, int ld4, int col4) {
    const float4* W4 = reinterpret_cast<const float4*>(W) + col4;
#pragma unroll 2
    for (int k = 0; k < K; k++) {
        float xv = x[k];
        const float4* wr = W4 + k * ld4;
        float4 w;
        w=__ldg(wr+0); acc[0]+=xv*w.x; acc[1]+=xv*w.y; acc[2]+=xv*w.z; acc[3]+=xv*w.w;
        w=__ldg(wr+1); acc[4]+=xv*w.x; acc[5]+=xv*w.y; acc[6]+=xv*w.z; acc[7]+=xv*w.w;
        w=__ldg(wr+2); acc[8]+=xv*w.x; acc[9]+=xv*w.y; acc[10]+=xv*w.z; acc[11]+=xv*w.w;
        w=__ldg(wr+3); acc[12]+=xv*w.x; acc[13]+=xv*w.y; acc[14]+=xv*w.z; acc[15]+=xv*w.w;
    }
}

// ---------------- CSR build ----------------
__global__ void k_zero_cnt() {
    int i = blockIdx.x * blockDim.x + threadIdx.x;
    if (i < NN) g_cnt[i] = 0;
}
__global__ void k_hist(const int* __restrict__ edst) {
    int e = blockIdx.x * blockDim.x + threadIdx.x;
    if (e < EE) atomicAdd(&g_cnt[edst[e]], 1);
}
#define SCAN_CH 49
__global__ void __launch_bounds__(1024) k_scan() {
    __shared__ int ssum[1024];
    int t = threadIdx.x;
    int beg = t * SCAN_CH;
    int end = min(beg + SCAN_CH, NN);
    int s = 0;
    for (int i = beg; i < end; i++) s += g_cnt[i];
    ssum[t] = s;
    __syncthreads();
    for (int off = 1; off < 1024; off <<= 1) {
        int v = (t >= off) ? ssum[t - off] : 0;
        __syncthreads();
        ssum[t] += v;
        __syncthreads();
    }
    int run = (t == 0) ? 0 : ssum[t - 1];
    for (int i = beg; i < end; i++) {
        g_rowptr[i] = run;
        g_fill[i]   = run;
        run += g_cnt[i];
    }
    if (t == 1023) g_rowptr[NN] = EE;
}
__global__ void k_perm(const int* __restrict__ edst) {
    int e = blockIdx.x * blockDim.x + threadIdx.x;
    if (e < EE) {
        int p = atomicAdd(&g_fill[edst[e]], 1);
        g_eid[p] = e;
    }
}

// ---------------- K1: edge geometry + RBF MLP -> per-edge records ----------------
__global__ void __launch_bounds__(256) k_edge1(
    const float* __restrict__ pos,
    const int* __restrict__ esrc, const int* __restrict__ edst,
    const float* __restrict__ W1, const float* __restrict__ B1,
    const float* __restrict__ W2, const float* __restrict__ B2,
    const float* __restrict__ WD, const float* __restrict__ BD,
    const float* __restrict__ WA, const float* __restrict__ BA,
    const float* __restrict__ expw)
{
    __shared__ float sRBF[64 * 53];
    __shared__ float sH1[64 * 65];
    __shared__ float sH2[64 * 65];
    __shared__ float sExp[64];
    __shared__ float sCut[64];

    int tid = threadIdx.x;
    int eb = blockIdx.x * 64;

    if (tid < 64) {
        int e = eb + tid;
        int s = __ldg(esrc + e), d = __ldg(edst + e);
        float vx = __ldg(pos + d*3+0) - __ldg(pos + s*3+0);
        float vy = __ldg(pos + d*3+1) - __ldg(pos + s*3+1);
        float vz = __ldg(pos + d*3+2) - __ldg(pos + s*3+2);
        float dist = sqrtf(vx*vx + vy*vy + vz*vz + 1e-9f);
        float rd = 1.0f / dist;
        g_Y1[e] = vx*rd; g_Y1[EE+e] = vy*rd; g_Y1[2*EE+e] = vz*rd;
        sExp[tid] = expf(-dist);
        sCut[tid] = (dist < 5.0f) ? 0.5f * (cosf(PI_OVER_CUT * dist) + 1.0f) : 0.0f;
    }
    __syncthreads();

    {   // RBF features, row stride 53
        const float OM = 1.0f - RBF_START;
        const float BD_ = 0.04f * OM;
        const float BETA = 1.0f / (BD_ * BD_);
        const float STEP = OM / 49.0f;
        for (int i = tid; i < 64 * NRBF; i += 256) {
            int el = i / NRBF, k = i - el * NRBF;
            float t = sExp[el] - (RBF_START + STEP * (float)k);
            sRBF[el * 53 + k] = sCut[el] * expf(-BETA * t * t);
        }
    }
    __syncthreads();

    int el = tid & 63, jg = tid >> 6;
    float v[16];

    load16(v, B1 + jg * 16);
    gemm16(v, sRBF + el * 53, NRBF, W1, 16, jg * 4);
#pragma unroll
    for (int q = 0; q < 16; q++) sH1[el*65 + jg*16 + q] = siluf(v[q]);
    __syncthreads();

    load16(v, B2 + jg * 16);
    gemm16(v, sH1 + el * 65, CC, W2, 16, jg * 4);
#pragma unroll
    for (int q = 0; q < 16; q++) sH2[el*65 + jg*16 + q] = siluf(v[q]);
    __syncthreads();

    const float* x2 = sH2 + el * 65;
    int e = eb + el;
    float ew[16];
    load16(ew, expw + jg * 16);

    // e0w = wd0 * exp_w  -> g_deg[e][0:64]
    load16(v, BD + jg * 16);
    gemm16(v, x2, CC, WD, 32, jg * 4);
#pragma unroll
    for (int q = 0; q < 16; q++) v[q] *= ew[q];
    store16(g_deg + (size_t)e * 128 + jg * 16, v);

    // e1w = wd1 * exp_w  -> g_deg[e][64:128]
    load16(v, BD + 64 + jg * 16);
    gemm16(v, x2, CC, WD, 32, 16 + jg * 4);
#pragma unroll
    for (int q = 0; q < 16; q++) v[q] *= ew[q];
    store16(g_deg + (size_t)e * 128 + 64 + jg * 16, v);

    // w_attn -> g_wat[e][k*64+c]
#pragma unroll
    for (int cb = 0; cb < 5; cb++) {
        load16(v, BA + cb * 64 + jg * 16);
        gemm16(v, x2, CC, WA, 80, cb * 16 + jg * 4);
        store16(g_wat + (size_t)e * 320 + cb * 64 + jg * 16, v);
    }
}

// ---------------- K2: CSR gather deg + project (2 nodes/block, 64 thr each) ----------------
__global__ void __launch_bounds__(128) k_node_deg(
    const float* __restrict__ embed_W, const int* __restrict__ atom,
    const float* __restrict__ P0, const float* __restrict__ P1)
{
    __shared__ float sa0[2][64];
    __shared__ float sa1[2][192];
    int half = threadIdx.x >> 6;
    int c = threadIdx.x & 63;
    int n = blockIdx.x * 2 + half;   // NN even, always < NN

    int beg = __ldg(g_rowptr + n), end = __ldg(g_rowptr + n + 1);
    float a0 = 0.f, a1x = 0.f, a1y = 0.f, a1z = 0.f;
    for (int i = beg; i < end; i++) {
        int e = __ldg(g_eid + i);
        float y0 = __ldg(g_Y1 + e), y1 = __ldg(g_Y1 + EE + e), y2 = __ldg(g_Y1 + 2*EE + e);
        const float* rec = g_deg + (size_t)e * 128;
        a0 += __ldg(rec + c);
        float w = __ldg(rec + 64 + c);
        a1x += w * y0; a1y += w * y1; a1z += w * y2;
    }
    sa0[half][c] = a0;
    sa1[half][c*3+0] = a1x; sa1[half][c*3+1] = a1y; sa1[half][c*3+2] = a1z;
    __syncthreads();

    float o0 = 0.f, o1x = 0.f, o1y = 0.f, o1z = 0.f;
#pragma unroll 4
    for (int k = 0; k < 64; k++) {
        float p0 = __ldg(P0 + k*64 + c);
        float p1 = __ldg(P1 + k*64 + c);
        o0  += sa0[half][k] * p0;
        o1x += sa1[half][k*3+0] * p1;
        o1y += sa1[half][k*3+1] * p1;
        o1z += sa1[half][k*3+2] * p1;
    }
    int at = __ldg(atom + n);
    g_f0[n*64 + c] = __ldg(embed_W + at*64 + c) + INV_DEG * o0;
    g_f1[n*192 + c*3 + 0] = INV_DEG * o1x;
    g_f1[n*192 + c*3 + 1] = INV_DEG * o1y;
    g_f1[n*192 + c*3 + 2] = INV_DEG * o1z;
}

// ---------------- K3: warp-per-edge messages + logits ----------------
__global__ void __launch_bounds__(256) k_edge2(
    const int* __restrict__ esrc, const float* __restrict__ alpha)
{
    __shared__ float sbuf[8 * 576];   // per warp: f0[64], f1[192], wat[320]
    int w = threadIdx.x >> 5;
    int l = threadIdx.x & 31;
    int e = blockIdx.x * 8 + w;
    float* buf = sbuf + w * 576;

    int src = __ldg(esrc + e);
    buf[l]      = __ldg(g_f0 + src*64 + l);
    buf[l + 32] = __ldg(g_f0 + src*64 + l + 32);
#pragma unroll
    for (int t = 0; t < 6; t++)
        buf[64 + t*32 + l] = __ldg(g_f1 + src*192 + t*32 + l);
    const float* wat = g_wat + (size_t)e * 320;
#pragma unroll
    for (int t = 0; t < 10; t++)
        buf[256 + t*32 + l] = __ldg(wat + t*32 + l);
    __syncwarp();

    float y0 = __ldg(g_Y1 + e), y1 = __ldg(g_Y1 + EE + e), y2 = __ldg(g_Y1 + 2*EE + e);
    float* msg = g_msg + (size_t)e * 256;

    float aA = 0.f, aB = 0.f;
#pragma unroll
    for (int halfc = 0; halfc < 2; halfc++) {
        int c = l + halfc * 32;
        float s0  = buf[c];
        float s1x = buf[64 + 3*c], s1y = buf[64 + 3*c + 1], s1z = buf[64 + 3*c + 2];
        float w0 = buf[256 + c];
        float w1 = buf[256 +  64 + c];
        float w2 = buf[256 + 128 + c];
        float w3 = buf[256 + 192 + c];
        float w4 = buf[256 + 256 + c];

        float sd = s1x*y0 + s1y*y1 + s1z*y2;
        float m0 = w0 * s0 + w3 * sd * RSQRT3;
        float cr0 = s1y*y2 - s1z*y1, cr1 = s1z*y0 - s1x*y2, cr2 = s1x*y1 - s1y*y0;
        float ws = w1 * s0;
        float m1x = ws*y0 + w2*s1x + w4*cr0*RSQRT2;
        float m1y = ws*y1 + w2*s1y + w4*cr1*RSQRT2;
        float m1z = ws*y2 + w2*s1z + w4*cr2*RSQRT2;

        msg[c] = m0;
        msg[64 + 3*c + 0] = m1x;
        msg[64 + 3*c + 1] = m1y;
        msg[64 + 3*c + 2] = m1z;

        float slr = 0.2f * m0 + 0.8f * m0 * sigf(m0);
        float contrib = slr * __ldg(alpha + c);
        if (halfc == 0) aA += contrib; else aB += contrib;
    }
    // reduce within 8-lane groups (channels of one head)
#pragma unroll
    for (int off = 4; off > 0; off >>= 1) {
        aA += __shfl_xor_sync(0xffffffffu, aA, off);
        aB += __shfl_xor_sync(0xffffffffu, aB, off);
    }
    if ((l & 7) == 0) {
        int g = l >> 3;                      // 0..3
        g_a[(size_t)e * 8 + g]     = aA;     // heads 0..3
        g_a[(size_t)e * 8 + 4 + g] = aB;     // heads 4..7
    }
}

// ---------------- K4: CSR gather softmax + attn agg + out proj ----------------
__global__ void __launch_bounds__(128) k_node_attn(
    const float* __restrict__ OP0, const float* __restrict__ OP1)
{
    __shared__ float sa0[2][64];
    __shared__ float sa1[2][192];
    int half = threadIdx.x >> 6;
    int c = threadIdx.x & 63;
    int n = blockIdx.x * 2 + half;
    int h = c >> 3;

    int beg = __ldg(g_rowptr + n), end = __ldg(g_rowptr + n + 1);

    float mx = -1e30f;
    for (int i = beg; i < end; i++) {
        int e = __ldg(g_eid + i);
        mx = fmaxf(mx, __ldg(g_a + (size_t)e*8 + h));
    }
    float z = 0.f;
    for (int i = beg; i < end; i++) {
        int e = __ldg(g_eid + i);
        z += expf(__ldg(g_a + (size_t)e*8 + h) - mx);
    }
    float inv_z = (end > beg) ? 1.0f / z : 0.f;

    float a0 = 0.f, a1x = 0.f, a1y = 0.f, a1z = 0.f;
    for (int i = beg; i < end; i++) {
        int e = __ldg(g_eid + i);
        float attn = expf(__ldg(g_a + (size_t)e*8 + h) - mx) * inv_z;
        const float* mp = g_msg + (size_t)e * 256;
        a0  += attn * __ldg(mp + c);
        a1x += attn * __ldg(mp + 64 + 3*c + 0);
        a1y += attn * __ldg(mp + 64 + 3*c + 1);
        a1z += attn * __ldg(mp + 64 + 3*c + 2);
    }
    sa0[half][c] = a0;
    sa1[half][c*3+0] = a1x; sa1[half][c*3+1] = a1y; sa1[half][c*3+2] = a1z;
    __syncthreads();

    float o0 = 0.f, o1x = 0.f, o1y = 0.f, o1z = 0.f;
#pragma unroll 4
    for (int k = 0; k < 64; k++) {
        float p0 = __ldg(OP0 + k*64 + c);
        float p1 = __ldg(OP1 + k*64 + c);
        o0  += sa0[half][k] * p0;
        o1x += sa1[half][k*3+0] * p1;
        o1y += sa1[half][k*3+1] * p1;
        o1z += sa1[half][k*3+2] * p1;
    }
    g_f0[n*64 + c] += o0;
    g_f1[n*192 + c*3 + 0] += o1x;
    g_f1[n*192 + c*3 + 1] += o1y;
    g_f1[n*192 + c*3 + 2] += o1z;
}

// ---------------- K5: FFN + final output ----------------
__global__ void __launch_bounds__(128) k_node_ffn(
    const float* __restrict__ W1s, const float* __restrict__ B1s,
    const float* __restrict__ W1v,
    const float* __restrict__ W2s, const float* __restrict__ B2s,
    const float* __restrict__ W2v,
    float* __restrict__ out)
{
    __shared__ float b0[32*65], b1[32*65], b2[32*65], b3[32*65];
    int tid = threadIdx.x;
    int nb = blockIdx.x * 32;

    for (int i = tid; i < 2048; i += 128) {
        int r = i >> 6, c = i & 63, n = nb + r;
        bool ok = (n < NN);
        b0[r*65+c] = ok ? g_f0[n*CC + c] : 0.f;
        b1[r*65+c] = ok ? g_f1[n*192 + c*3 + 0] : 0.f;
        b2[r*65+c] = ok ? g_f1[n*192 + c*3 + 1] : 0.f;
        b3[r*65+c] = ok ? g_f1[n*192 + c*3 + 2] : 0.f;
    }
    __syncthreads();

    int nl = tid & 31, jg = tid >> 5;
    int n = nb + nl;
    bool valid = (n < NN);

    float ms[16], gt[16], mv[48];
    {
        float hA[16], hB[16];
        load16(hA, B1s + jg * 16);
        load16(hB, B1s + 64 + jg * 16);
        gemm16(hA, b0 + nl*65, CC, W1s, 32, jg * 4);
        gemm16(hB, b0 + nl*65, CC, W1s, 32, 16 + jg * 4);
#pragma unroll
        for (int q = 0; q < 16; q++) { ms[q] = siluf(hA[q]); gt[q] = sigf(hB[q]); }
        const float* planes[3] = { b1, b2, b3 };
#pragma unroll
        for (int i = 0; i < 3; i++) {
            float t[16]; zero16(t);
            gemm16(t, planes[i] + nl*65, CC, W1v, 16, jg * 4);
#pragma unroll
            for (int q = 0; q < 16; q++) mv[i*16 + q] = t[q] * gt[q];
        }
    }
    __syncthreads();
#pragma unroll
    for (int q = 0; q < 16; q++) {
        int c = jg * 16 + q;
        b0[nl*65 + c] = ms[q];
        b1[nl*65 + c] = mv[q];
        b2[nl*65 + c] = mv[16 + q];
        b3[nl*65 + c] = mv[32 + q];
    }
    __syncthreads();

    if (!valid) return;

    float v[16];
    load16(v, B2s + jg * 16);
    gemm16(v, b0 + nl*65, CC, W2s, 16, jg * 4);
#pragma unroll
    for (int q = 0; q < 16; q++) {
        int c = jg * 16 + q;
        out[(size_t)n*256 + c] = g_f0[n*CC + c] + v[q];
    }
    const float* planes[3] = { b1, b2, b3 };
#pragma unroll
    for (int i = 0; i < 3; i++) {
        float t[16]; zero16(t);
        gemm16(t, planes[i] + nl*65, CC, W2v, 16, jg * 4);
#pragma unroll
        for (int q = 0; q < 16; q++) {
            int c = jg * 16 + q;
            out[(size_t)n*256 + 64 + c*3 + i] = g_f1[n*192 + c*3 + i] + t[q];
        }
    }
}

// ---------------- launch ----------------
extern "C" void kernel_launch(void* const* d_in, const int* in_sizes, int n_in,
                              void* d_out, int out_size)
{
    const float* pos   = (const float*)d_in[0];
    const float* embed = (const float*)d_in[1];
    const float* expw  = (const float*)d_in[2];
    const float* W1    = (const float*)d_in[3];
    const float* B1    = (const float*)d_in[4];
    const float* W2    = (const float*)d_in[5];
    const float* B2    = (const float*)d_in[6];
    const float* WD    = (const float*)d_in[7];
    const float* BDg   = (const float*)d_in[8];
    const float* WA    = (const float*)d_in[9];
    const float* BA    = (const float*)d_in[10];
    const float* P0    = (const float*)d_in[11];
    const float* P1    = (const float*)d_in[12];
    const float* alpha = (const float*)d_in[13];
    const float* OP0   = (const float*)d_in[14];
    const float* OP1   = (const float*)d_in[15];
    const float* W1s   = (const float*)d_in[16];
    const float* B1s   = (const float*)d_in[17];
    const float* W1v   = (const float*)d_in[18];
    const float* W2s   = (const float*)d_in[19];
    const float* B2s   = (const float*)d_in[20];
    const float* W2v   = (const float*)d_in[21];
    const int*   atom  = (const int*)d_in[22];
    const int*   esrc  = (const int*)d_in[23];
    const int*   edst  = (const int*)d_in[24];
    float* out = (float*)d_out;

    k_zero_cnt<<<(NN + 255) / 256, 256>>>();
    k_hist<<<(EE + 255) / 256, 256>>>(edst);
    k_scan<<<1, 1024>>>();
    k_perm<<<(EE + 255) / 256, 256>>>(edst);
    k_edge1<<<EE / 64, 256>>>(pos, esrc, edst, W1, B1, W2, B2, WD, BDg, WA, BA, expw);
    k_node_deg<<<NN / 2, 128>>>(embed, atom, P0, P1);
    k_edge2<<<EE / 8, 256>>>(esrc, alpha);
    k_node_attn<<<NN / 2, 128>>>(OP0, OP1);
    k_node_ffn<<<(NN + 31) / 32, 128>>>(W1s, B1s, W1v, W2s, B2s, W2v, out);
}